// round 1
// baseline (speedup 1.0000x reference)
#include <cuda_runtime.h>

#define DEV_INLINE __device__ __forceinline__

constexpr int B = 8, H = 128, W = 256, C = 128, D = 128;

// -------- device scratch (no allocations allowed) --------
__device__ float g_a[B * H * W];  // a = conv1(x) pre-relu, [B,H,W]
__device__ float g_S[B * H * W];  // broadcast scalar field for z

// ============================================================
// Phase 1: a[b,h,w] = sum_{k,c} x[b,h,w+k-4,c] * w1[k,c] + b1
// ============================================================
constexpr int P1_TW = 64;
constexpr int P1_COLS = P1_TW + 8;   // 4-halo each side
constexpr int P1_XS = 132;           // padded stride (bank-conflict control)

__global__ void __launch_bounds__(256) phase1_kernel(const float* __restrict__ x,
                                                     const float* __restrict__ w1,
                                                     const float* __restrict__ b1) {
  __shared__ float xs[P1_COLS * P1_XS];
  __shared__ float w1s[9 * C];
  const int w0 = blockIdx.x * P1_TW;
  const int h = blockIdx.y, b = blockIdx.z;
  const float* xrow = x + ((size_t)(b * H + h) * W) * C;

  for (int idx = threadIdx.x; idx < 9 * C / 4; idx += 256)
    ((float4*)w1s)[idx] = ((const float4*)w1)[idx];

  for (int idx = threadIdx.x; idx < P1_COLS * (C / 4); idx += 256) {
    int col = idx >> 5, c4 = idx & 31;
    int w = w0 - 4 + col;
    float4 v = make_float4(0.f, 0.f, 0.f, 0.f);
    if (w >= 0 && w < W) v = ((const float4*)(xrow + (size_t)w * C))[c4];
    ((float4*)(xs + col * P1_XS))[c4] = v;
  }
  __syncthreads();

  const int p = threadIdx.x >> 2, qd = threadIdx.x & 3;  // 4 threads per pixel
  float acc = 0.f;
#pragma unroll
  for (int k = 0; k < 9; k++) {
    const float* xc = xs + (p + k) * P1_XS;
    const float* wk = w1s + k * C;
#pragma unroll
    for (int j = 0; j < 32; j++) {
      int c = qd + 4 * j;  // interleaved channels -> conflict-free LDS
      acc += xc[c] * wk[c];
    }
  }
  acc += __shfl_xor_sync(0xffffffffu, acc, 1);
  acc += __shfl_xor_sync(0xffffffffu, acc, 2);
  if (qd == 0) g_a[(size_t)(b * H + h) * W + w0 + p] = acc + b1[0];
}

// ============================================================
// Phase 2: S[b,h,w] scalar field.
//  t = relu(a);  u[hh,w] = relu(a[hh,w] + sum_k s[k]*t[hh-1,w+k-4]) (hh>=1)
//  h=0:     S=u[0]+t[H-2]        (z row source g=H-1)
//  h=1:     S=u[1]               (g=0)
//  2..H-3:  S=u[h]+t[h-2]        (g=h-1)
//  h=H-2:   S=u[H-1]+t[H-3]      (g=H-2)
//  h=H-1:   S=t[H-2]             (g=H-1)
// ============================================================
__global__ void __launch_bounds__(256) phase2_kernel(const float* __restrict__ w1) {
  __shared__ float s[9];
  const int h = blockIdx.x, b = blockIdx.y;
  const int w = threadIdx.x;
  if (threadIdx.x < 9) {
    float acc = 0.f;
    for (int c = 0; c < C; c++) acc += w1[threadIdx.x * C + c];
    s[threadIdx.x] = acc;
  }
  __syncthreads();

  const float* ab = g_a + (size_t)b * H * W;
  float Sv;
  if (h == H - 1) {
    Sv = fmaxf(ab[(H - 2) * W + w], 0.f);
  } else {
    int hh = (h == H - 2) ? (H - 1) : h;
    float cy = ab[hh * W + w];
    if (hh >= 1) {
      const float* ap = ab + (hh - 1) * W;
#pragma unroll
      for (int k = 0; k < 9; k++) {
        int ww = w + k - 4;
        if (ww >= 0 && ww < W) cy += s[k] * fmaxf(ap[ww], 0.f);
      }
    }
    float u = fmaxf(cy, 0.f);
    int tr = (h == 0) ? (H - 2) : (h == 1 ? -1 : (h <= H - 3 ? h - 2 : H - 3));
    Sv = u + ((tr >= 0) ? fmaxf(ab[tr * W + w], 0.f) : 0.f);
  }
  g_S[(size_t)(b * H + h) * W + w] = Sv;
}

// ============================================================
// Phase 3 (fused passes 3+4):
//  z[w] = x[g(h),w,:] + S[h,w];  v = relu(z@W2+b2)
//  p[w] = z[w] + v[w-1] (w>0);   r = relu(p@W2+b2)
//  q[w] = r[w] + p[(w-1) mod W]  for w<=W-3
//  q[W-2] = r[W-1] + p[W-2];     q[W-1] = p[W-1]
// Tile: 64 output cols + 2-col left halo (wrap), per (b,h).
// ============================================================
constexpr int WT = 64;
constexpr int NI = WT + 2;   // 66 staged columns
constexpr int ZS = 132;      // padded smem stride
constexpr int SM_FLOATS = 2 * NI * ZS + C * D + D + 72;
constexpr int SM_BYTES = SM_FLOATS * 4;

template <int NR>
DEV_INLINE void gemm_rows(const float* __restrict__ src,
                          const float* __restrict__ w2s,
                          const float* __restrict__ b2s,
                          int i0, int i1, int i2, int n0,
                          float acc0[8], float acc1[8], float acc2[8]) {
#pragma unroll
  for (int j = 0; j < 8; j++) {
    float bj = b2s[n0 + j];
    acc0[j] = bj; acc1[j] = bj;
    if (NR > 2) acc2[j] = bj;
  }
  const float* s0 = src + i0 * ZS;
  const float* s1 = src + i1 * ZS;
  const float* s2 = src + ((NR > 2) ? i2 : i0) * ZS;
#pragma unroll 2
  for (int k = 0; k < C; k += 4) {
    float4 z0 = *(const float4*)(s0 + k);
    float4 z1 = *(const float4*)(s1 + k);
    float4 z2 = make_float4(0.f, 0.f, 0.f, 0.f);
    if (NR > 2) z2 = *(const float4*)(s2 + k);
#pragma unroll
    for (int kk = 0; kk < 4; kk++) {
      const float* wr = w2s + (k + kk) * D + n0;
      float4 wa = *(const float4*)wr;
      float4 wb = *(const float4*)(wr + 4);
      float f0 = ((const float*)&z0)[kk];
      float f1 = ((const float*)&z1)[kk];
      acc0[0] += f0 * wa.x; acc0[1] += f0 * wa.y; acc0[2] += f0 * wa.z; acc0[3] += f0 * wa.w;
      acc0[4] += f0 * wb.x; acc0[5] += f0 * wb.y; acc0[6] += f0 * wb.z; acc0[7] += f0 * wb.w;
      acc1[0] += f1 * wa.x; acc1[1] += f1 * wa.y; acc1[2] += f1 * wa.z; acc1[3] += f1 * wa.w;
      acc1[4] += f1 * wb.x; acc1[5] += f1 * wb.y; acc1[6] += f1 * wb.z; acc1[7] += f1 * wb.w;
      if (NR > 2) {
        float f2 = ((const float*)&z2)[kk];
        acc2[0] += f2 * wa.x; acc2[1] += f2 * wa.y; acc2[2] += f2 * wa.z; acc2[3] += f2 * wa.w;
        acc2[4] += f2 * wb.x; acc2[5] += f2 * wb.y; acc2[6] += f2 * wb.z; acc2[7] += f2 * wb.w;
      }
    }
  }
}

DEV_INLINE void store8relu(float* __restrict__ d, const float acc[8]) {
  float4 a = make_float4(fmaxf(acc[0], 0.f), fmaxf(acc[1], 0.f), fmaxf(acc[2], 0.f), fmaxf(acc[3], 0.f));
  float4 b = make_float4(fmaxf(acc[4], 0.f), fmaxf(acc[5], 0.f), fmaxf(acc[6], 0.f), fmaxf(acc[7], 0.f));
  *(float4*)d = a;
  *(float4*)(d + 4) = b;
}

DEV_INLINE void write_q(float* __restrict__ qbase, int w0, int i, int n0,
                        const float acc[8], const float* __restrict__ ps) {
  if (i < 2) return;
  const int w = w0 - 2 + i;          // i in [2,66) -> w in [w0, w0+63], no wrap
  if (w == W - 2) return;            // r[W-2] is discarded by the reference
  if (w == W - 1) {
    // q[W-2] = r[W-1] + p[W-2];  q[W-1] = p[W-1]
    const float* p2 = ps + 64 * ZS + n0;
    const float* p1 = ps + 65 * ZS + n0;
    float4 a = make_float4(fmaxf(acc[0], 0.f) + p2[0], fmaxf(acc[1], 0.f) + p2[1],
                           fmaxf(acc[2], 0.f) + p2[2], fmaxf(acc[3], 0.f) + p2[3]);
    float4 b = make_float4(fmaxf(acc[4], 0.f) + p2[4], fmaxf(acc[5], 0.f) + p2[5],
                           fmaxf(acc[6], 0.f) + p2[6], fmaxf(acc[7], 0.f) + p2[7]);
    *(float4*)(qbase + (size_t)(W - 2) * C + n0) = a;
    *(float4*)(qbase + (size_t)(W - 2) * C + n0 + 4) = b;
    *(float4*)(qbase + (size_t)(W - 1) * C + n0) = *(const float4*)p1;
    *(float4*)(qbase + (size_t)(W - 1) * C + n0 + 4) = *(const float4*)(p1 + 4);
  } else {
    const float* pm = ps + (i - 1) * ZS + n0;
    float4 a = make_float4(fmaxf(acc[0], 0.f) + pm[0], fmaxf(acc[1], 0.f) + pm[1],
                           fmaxf(acc[2], 0.f) + pm[2], fmaxf(acc[3], 0.f) + pm[3]);
    float4 b = make_float4(fmaxf(acc[4], 0.f) + pm[4], fmaxf(acc[5], 0.f) + pm[5],
                           fmaxf(acc[6], 0.f) + pm[6], fmaxf(acc[7], 0.f) + pm[7]);
    float* d = qbase + (size_t)w * C + n0;
    *(float4*)d = a;
    *(float4*)(d + 4) = b;
  }
}

__global__ void __launch_bounds__(512) phase3_kernel(const float* __restrict__ x,
                                                     const float* __restrict__ w2g,
                                                     const float* __restrict__ b2g,
                                                     float* __restrict__ q) {
  extern __shared__ float sm[];
  float* zs = sm;                      // NI x ZS : z, later p (in place)
  float* vs = zs + NI * ZS;            // NI x ZS : v
  float* w2s = vs + NI * ZS;           // C x D   : center tap of w2
  float* b2s = w2s + C * D;            // D
  float* scol = b2s + D;               // NI scalars

  const int tid = threadIdx.x;
  const int w0 = blockIdx.x * WT;
  const int h = blockIdx.y, b = blockIdx.z;
  const int gh = (h == 0 || h == H - 1) ? (H - 1) : ((h <= H - 3) ? h - 1 : H - 2);
  const float* xrow = x + ((size_t)(b * H + gh) * W) * C;
  const float* Srow = g_S + (size_t)(b * H + h) * W;

  for (int i = tid; i < NI; i += 512) scol[i] = Srow[(w0 - 2 + i) & (W - 1)];
  for (int idx = tid; idx < C * D / 4; idx += 512)
    ((float4*)w2s)[idx] = ((const float4*)(w2g + 4 * C * D))[idx];  // w2[0,4,:,:]
  if (tid < D / 4) ((float4*)b2s)[tid] = ((const float4*)b2g)[tid];
  __syncthreads();

  // stage z = x[g(h), J, :] + S[h, J]
  for (int idx = tid; idx < NI * (C / 4); idx += 512) {
    int i = idx >> 5, c4 = idx & 31;
    int J = (w0 - 2 + i) & (W - 1);
    float4 v = ((const float4*)(xrow + (size_t)J * C))[c4];
    float sv = scol[i];
    v.x += sv; v.y += sv; v.z += sv; v.w += sv;
    ((float4*)(zs + i * ZS))[c4] = v;
  }
  __syncthreads();

  const int tx = tid & 15, ty = tid >> 4;
  const int n0 = tx * 8;
  const int i0 = ty, i1 = ty + 32;
  const int i2 = (ty < 2) ? (64 + ty) : -1;
  float acc0[8], acc1[8], acc2[8];

  // GEMM 1: v = relu(z @ W2 + b2)
  if (i2 >= 0) gemm_rows<3>(zs, w2s, b2s, i0, i1, i2, n0, acc0, acc1, acc2);
  else         gemm_rows<2>(zs, w2s, b2s, i0, i1, i2, n0, acc0, acc1, acc2);
  store8relu(vs + i0 * ZS + n0, acc0);
  store8relu(vs + i1 * ZS + n0, acc1);
  if (i2 >= 0) store8relu(vs + i2 * ZS + n0, acc2);
  __syncthreads();

  // p = z + v[w-1] in place (skip global column 0: p[0]=z[0])
  for (int idx = tid; idx < (NI - 1) * (C / 4); idx += 512) {
    int i = 1 + (idx >> 5), c4 = idx & 31;
    if (!(w0 == 0 && i == 2)) {
      float4 pv = ((float4*)(zs + i * ZS))[c4];
      float4 vv = ((const float4*)(vs + (i - 1) * ZS))[c4];
      pv.x += vv.x; pv.y += vv.y; pv.z += vv.z; pv.w += vv.w;
      ((float4*)(zs + i * ZS))[c4] = pv;
    }
  }
  __syncthreads();

  // GEMM 2: r = relu(p @ W2 + b2), fused epilogue writes q
  if (i2 >= 0) gemm_rows<3>(zs, w2s, b2s, i0, i1, i2, n0, acc0, acc1, acc2);
  else         gemm_rows<2>(zs, w2s, b2s, i0, i1, i2, n0, acc0, acc1, acc2);

  float* qbase = q + ((size_t)(b * H + h) * W) * C;
  write_q(qbase, w0, i0, n0, acc0, zs);
  write_q(qbase, w0, i1, n0, acc1, zs);
  if (i2 >= 0) write_q(qbase, w0, i2, n0, acc2, zs);
}

// ============================================================
extern "C" void kernel_launch(void* const* d_in, const int* in_sizes, int n_in,
                              void* d_out, int out_size) {
  (void)in_sizes; (void)n_in; (void)out_size;
  const float* x  = (const float*)d_in[0];
  const float* w1 = (const float*)d_in[1];
  const float* b1 = (const float*)d_in[2];
  const float* w2 = (const float*)d_in[3];
  const float* b2 = (const float*)d_in[4];
  float* q = (float*)d_out;

  cudaFuncSetAttribute(phase3_kernel, cudaFuncAttributeMaxDynamicSharedMemorySize, SM_BYTES);

  phase1_kernel<<<dim3(W / P1_TW, H, B), 256>>>(x, w1, b1);
  phase2_kernel<<<dim3(H, B), 256>>>(w1);
  phase3_kernel<<<dim3(W / WT, H, B), 512, SM_BYTES>>>(x, w2, b2, q);
}

// round 2
// speedup vs baseline: 1.6764x; 1.6764x over previous
#include <cuda_runtime.h>

#define DEV_INLINE __device__ __forceinline__
using u64 = unsigned long long;

constexpr int B = 8, H = 128, W = 256, C = 128, D = 128;

// -------- device scratch (no allocations allowed) --------
__device__ float g_a[B * H * W];  // a = conv1(x) pre-relu, [B,H,W]
__device__ float g_S[B * H * W];  // broadcast scalar field for z

// ============================================================
// Phase 1: a[b,h,w] = sum_{k,c} x[b,h,w+k-4,c] * w1[k,c] + b1
// ============================================================
constexpr int P1_TW = 64;
constexpr int P1_COLS = P1_TW + 8;   // 4-halo each side
constexpr int P1_XS = 132;           // padded stride

__global__ void __launch_bounds__(256) phase1_kernel(const float* __restrict__ x,
                                                     const float* __restrict__ w1,
                                                     const float* __restrict__ b1) {
  __shared__ float xs[P1_COLS * P1_XS];
  __shared__ float w1s[9 * C];
  const int w0 = blockIdx.x * P1_TW;
  const int h = blockIdx.y, b = blockIdx.z;
  const float* xrow = x + ((size_t)(b * H + h) * W) * C;

  for (int idx = threadIdx.x; idx < 9 * C / 4; idx += 256)
    ((float4*)w1s)[idx] = ((const float4*)w1)[idx];

  for (int idx = threadIdx.x; idx < P1_COLS * (C / 4); idx += 256) {
    int col = idx >> 5, c4 = idx & 31;
    int w = w0 - 4 + col;
    float4 v = make_float4(0.f, 0.f, 0.f, 0.f);
    if (w >= 0 && w < W) v = ((const float4*)(xrow + (size_t)w * C))[c4];
    ((float4*)(xs + col * P1_XS))[c4] = v;
  }
  __syncthreads();

  const int p = threadIdx.x >> 2, qd = threadIdx.x & 3;  // 4 threads per pixel
  float acc = 0.f;
#pragma unroll
  for (int k = 0; k < 9; k++) {
    const float* xc = xs + (p + k) * P1_XS;
    const float* wk = w1s + k * C;
#pragma unroll
    for (int j = 0; j < 32; j++) {
      int c = qd + 4 * j;
      acc += xc[c] * wk[c];
    }
  }
  acc += __shfl_xor_sync(0xffffffffu, acc, 1);
  acc += __shfl_xor_sync(0xffffffffu, acc, 2);
  if (qd == 0) g_a[(size_t)(b * H + h) * W + w0 + p] = acc + b1[0];
}

// ============================================================
// Phase 2: S[b,h,w] scalar field (see derivation comments, round 1)
// ============================================================
__global__ void __launch_bounds__(256) phase2_kernel(const float* __restrict__ w1) {
  __shared__ float s[9];
  const int h = blockIdx.x, b = blockIdx.y;
  const int w = threadIdx.x;
  if (threadIdx.x < 9) {
    float acc = 0.f;
    for (int c = 0; c < C; c++) acc += w1[threadIdx.x * C + c];
    s[threadIdx.x] = acc;
  }
  __syncthreads();

  const float* ab = g_a + (size_t)b * H * W;
  float Sv;
  if (h == H - 1) {
    Sv = fmaxf(ab[(H - 2) * W + w], 0.f);
  } else {
    int hh = (h == H - 2) ? (H - 1) : h;
    float cy = ab[hh * W + w];
    if (hh >= 1) {
      const float* ap = ab + (hh - 1) * W;
#pragma unroll
      for (int k = 0; k < 9; k++) {
        int ww = w + k - 4;
        if (ww >= 0 && ww < W) cy += s[k] * fmaxf(ap[ww], 0.f);
      }
    }
    float u = fmaxf(cy, 0.f);
    int tr = (h == 0) ? (H - 2) : (h == 1 ? -1 : (h <= H - 3 ? h - 2 : H - 3));
    Sv = u + ((tr >= 0) ? fmaxf(ab[tr * W + w], 0.f) : 0.f);
  }
  g_S[(size_t)(b * H + h) * W + w] = Sv;
}

// ============================================================
// Phase 3 (fused passes 3+4), FFMA2 version.
//  W-tile = 128 output cols, M = 130 staged rows (2-col wrap halo), pad 136.
//  288 threads: 17 row-groups x 16 col-groups, thread tile 8 rows x 8 cols.
//  Accumulators are f32x2 column-pairs -> fma.rn.f32x2.
// ============================================================
constexpr int WT = 128;
constexpr int NI = WT + 2;   // 130 staged columns
constexpr int MP = 136;      // padded to 17*8 rows
constexpr int ZS = 132;      // padded smem k-stride (132*4 % 16 == 0)
constexpr int NT = 288;
constexpr int SM_FLOATS = 2 * MP * ZS + C * D + D + MP;
constexpr int SM_BYTES = SM_FLOATS * 4;   // 210208 B

DEV_INLINE u64 pack2f(float lo, float hi) {
  u64 r; asm("mov.b64 %0,{%1,%2};" : "=l"(r) : "f"(lo), "f"(hi)); return r;
}
DEV_INLINE u64 dup2f(float v) {
  u64 r; asm("mov.b64 %0,{%1,%1};" : "=l"(r) : "f"(v)); return r;
}
DEV_INLINE void fma2(u64& d, u64 a, u64 b) {
  asm("fma.rn.f32x2 %0,%1,%2,%0;" : "+l"(d) : "l"(a), "l"(b));
}
DEV_INLINE float2 unpk(u64 v) {
  float2 f; asm("mov.b64 {%0,%1},%2;" : "=f"(f.x), "=f"(f.y) : "l"(v)); return f;
}

// GEMM: rows [base, base+8) x cols [n0, n0+8), K = C over smem src (stride ZS).
DEV_INLINE void gemm8x8(const float* __restrict__ src, int base,
                        const float* __restrict__ w2s,
                        const float* __restrict__ b2s, int n0, u64 acc[8][4]) {
  float4 bA = *(const float4*)(b2s + n0);
  float4 bB = *(const float4*)(b2s + n0 + 4);
#pragma unroll
  for (int r = 0; r < 8; r++) {
    acc[r][0] = pack2f(bA.x, bA.y);
    acc[r][1] = pack2f(bA.z, bA.w);
    acc[r][2] = pack2f(bB.x, bB.y);
    acc[r][3] = pack2f(bB.z, bB.w);
  }
  const float* s = src + (size_t)base * ZS;
#pragma unroll 2
  for (int k0 = 0; k0 < C; k0 += 4) {
    float4 a[8];
#pragma unroll
    for (int r = 0; r < 8; r++) a[r] = *(const float4*)(s + r * ZS + k0);
#pragma unroll
    for (int kk = 0; kk < 4; kk++) {
      const ulonglong2* wp = (const ulonglong2*)(w2s + (k0 + kk) * D + n0);
      ulonglong2 wA = wp[0];           // cols n0..n0+3 as 2 packed pairs
      ulonglong2 wB = wp[1];           // cols n0+4..n0+7
#pragma unroll
      for (int r = 0; r < 8; r++) {
        float av = (kk == 0) ? a[r].x : (kk == 1) ? a[r].y : (kk == 2) ? a[r].z : a[r].w;
        u64 ad = dup2f(av);
        fma2(acc[r][0], ad, wA.x);
        fma2(acc[r][1], ad, wA.y);
        fma2(acc[r][2], ad, wB.x);
        fma2(acc[r][3], ad, wB.y);
      }
    }
  }
}

DEV_INLINE void relu_store8(float* __restrict__ d, const u64 acc[4]) {
  float2 p0 = unpk(acc[0]), p1 = unpk(acc[1]), p2 = unpk(acc[2]), p3 = unpk(acc[3]);
  float4 A = make_float4(fmaxf(p0.x, 0.f), fmaxf(p0.y, 0.f), fmaxf(p1.x, 0.f), fmaxf(p1.y, 0.f));
  float4 Bv = make_float4(fmaxf(p2.x, 0.f), fmaxf(p2.y, 0.f), fmaxf(p3.x, 0.f), fmaxf(p3.y, 0.f));
  *(float4*)d = A;
  *(float4*)(d + 4) = Bv;
}

__global__ void __launch_bounds__(NT, 1) phase3_kernel(const float* __restrict__ x,
                                                       const float* __restrict__ w2g,
                                                       const float* __restrict__ b2g,
                                                       float* __restrict__ q) {
  extern __shared__ float sm[];
  float* zs = sm;                      // MP x ZS : z, later p (in place)
  float* vs = zs + MP * ZS;            // MP x ZS : v
  float* w2s = vs + MP * ZS;           // C x D   : center tap of w2 (row-major k,n)
  float* b2s = w2s + C * D;            // D
  float* scol = b2s + D;               // MP scalars

  const int tid = threadIdx.x;
  const int w0 = blockIdx.x * WT;
  const int h = blockIdx.y, b = blockIdx.z;
  const int gh = (h == 0 || h == H - 1) ? (H - 1) : ((h <= H - 3) ? h - 1 : H - 2);
  const float* xrow = x + ((size_t)(b * H + gh) * W) * C;
  const float* Srow = g_S + (size_t)(b * H + h) * W;

  for (int i = tid; i < MP; i += NT) scol[i] = (i < NI) ? Srow[(w0 - 2 + i) & (W - 1)] : 0.f;
  for (int idx = tid; idx < C * D / 4; idx += NT)
    ((float4*)w2s)[idx] = ((const float4*)(w2g + 4 * C * D))[idx];  // w2[0,4,:,:]
  for (int i = tid; i < D; i += NT) b2s[i] = b2g[i];
  __syncthreads();

  // stage z = x[g(h), J, :] + S[h, J]; zero the pad rows
  for (int idx = tid; idx < MP * (C / 4); idx += NT) {
    int i = idx >> 5, c4 = idx & 31;
    float4 v = make_float4(0.f, 0.f, 0.f, 0.f);
    if (i < NI) {
      int J = (w0 - 2 + i) & (W - 1);
      v = ((const float4*)(xrow + (size_t)J * C))[c4];
      float sv = scol[i];
      v.x += sv; v.y += sv; v.z += sv; v.w += sv;
    }
    ((float4*)(zs + i * ZS))[c4] = v;
  }
  __syncthreads();

  const int cg = tid & 15, rg = tid >> 4;   // rg in 0..17
  const int n0 = cg * 8, base = rg * 8;
  const bool act = (rg < 17);
  u64 acc[8][4];

  // GEMM 1: v = relu(z @ W2 + b2)
  if (act) {
    gemm8x8(zs, base, w2s, b2s, n0, acc);
#pragma unroll
    for (int r = 0; r < 8; r++) relu_store8(vs + (size_t)(base + r) * ZS + n0, acc[r]);
  }
  __syncthreads();

  // p = z + v[w-1] in place (skip global column 0: p[0]=z[0])
  for (int idx = tid; idx < (NI - 1) * (C / 4); idx += NT) {
    int i = 1 + (idx >> 5), c4 = idx & 31;
    if (!(w0 == 0 && i == 2)) {
      float4 pv = ((float4*)(zs + i * ZS))[c4];
      float4 vv = ((const float4*)(vs + (i - 1) * ZS))[c4];
      pv.x += vv.x; pv.y += vv.y; pv.z += vv.z; pv.w += vv.w;
      ((float4*)(zs + i * ZS))[c4] = pv;
    }
  }
  __syncthreads();

  // GEMM 2: r = relu(p @ W2 + b2), fused epilogue writes q
  if (act) {
    gemm8x8(zs, base, w2s, b2s, n0, acc);
    float* qbase = q + ((size_t)(b * H + h) * W) * C;
#pragma unroll
    for (int r = 0; r < 8; r++) {
      int i = base + r;
      if (i < 2 || i >= NI) continue;
      int w = w0 - 2 + i;
      if (w == W - 2) continue;          // r[W-2] discarded by the reference
      float2 p0 = unpk(acc[r][0]), p1 = unpk(acc[r][1]), p2 = unpk(acc[r][2]), p3 = unpk(acc[r][3]);
      float rr0 = fmaxf(p0.x, 0.f), rr1 = fmaxf(p0.y, 0.f), rr2 = fmaxf(p1.x, 0.f), rr3 = fmaxf(p1.y, 0.f);
      float rr4 = fmaxf(p2.x, 0.f), rr5 = fmaxf(p2.y, 0.f), rr6 = fmaxf(p3.x, 0.f), rr7 = fmaxf(p3.y, 0.f);
      const float* pm = zs + (size_t)(i - 1) * ZS + n0;   // p[w-1] (wrap via halo)
      float4 A = make_float4(rr0 + pm[0], rr1 + pm[1], rr2 + pm[2], rr3 + pm[3]);
      float4 Bv = make_float4(rr4 + pm[4], rr5 + pm[5], rr6 + pm[6], rr7 + pm[7]);
      if (w == W - 1) {
        // q[W-2] = r[W-1] + p[W-2];  q[W-1] = p[W-1]
        const float* pl = zs + (size_t)i * ZS + n0;        // p[W-1]
        *(float4*)(qbase + (size_t)(W - 2) * C + n0) = A;
        *(float4*)(qbase + (size_t)(W - 2) * C + n0 + 4) = Bv;
        *(float4*)(qbase + (size_t)(W - 1) * C + n0) = *(const float4*)pl;
        *(float4*)(qbase + (size_t)(W - 1) * C + n0 + 4) = *(const float4*)(pl + 4);
      } else {
        float* d = qbase + (size_t)w * C + n0;
        *(float4*)d = A;
        *(float4*)(d + 4) = Bv;
      }
    }
  }
}

// ============================================================
extern "C" void kernel_launch(void* const* d_in, const int* in_sizes, int n_in,
                              void* d_out, int out_size) {
  (void)in_sizes; (void)n_in; (void)out_size;
  const float* x  = (const float*)d_in[0];
  const float* w1 = (const float*)d_in[1];
  const float* b1 = (const float*)d_in[2];
  const float* w2 = (const float*)d_in[3];
  const float* b2 = (const float*)d_in[4];
  float* q = (float*)d_out;

  cudaFuncSetAttribute(phase3_kernel, cudaFuncAttributeMaxDynamicSharedMemorySize, SM_BYTES);

  phase1_kernel<<<dim3(W / P1_TW, H, B), 256>>>(x, w1, b1);
  phase2_kernel<<<dim3(H, B), 256>>>(w1);
  phase3_kernel<<<dim3(W / WT, H, B), NT, SM_BYTES>>>(x, w2, b2, q);
}